// round 14
// baseline (speedup 1.0000x reference)
#include <cuda_runtime.h>
#include <cstdint>

#define POOL 7
#define NUM_ROIS 512
#define IMG_H 128
#define IMG_W 128
#define CH 1024

// 2 cells per 256-thread block: threads 0-127 -> cell0, 128-255 -> cell1.
// Blackwell 256-bit loads: each thread loads 8 consecutive floats per corner
// with ONE ld.global.v8.f32 -> 4 load instructions/thread (was 8), same bytes,
// warp-instruction covers 1024B contiguous. Stores: 2x __stcs float4 (proven).

struct f8 { float v[8]; };

static __device__ __forceinline__ f8 ldg256(const float* p) {
    f8 r;
    asm volatile("ld.global.v8.f32 {%0,%1,%2,%3,%4,%5,%6,%7}, [%8];"
                 : "=f"(r.v[0]), "=f"(r.v[1]), "=f"(r.v[2]), "=f"(r.v[3]),
                   "=f"(r.v[4]), "=f"(r.v[5]), "=f"(r.v[6]), "=f"(r.v[7])
                 : "l"(p));
    return r;
}

__global__ __launch_bounds__(256, 8)
void roi_pool_kernel(const float* __restrict__ img,
                     const int* __restrict__ rois,
                     float* __restrict__ out) {
    const int half = threadIdx.x >> 7;        // 0 or 1
    const int lane = threadIdx.x & 127;       // 0..127
    const int cell = blockIdx.x * 2 + half;   // roi*49 + py*7 + px

    const int roi  = cell / (POOL * POOL);
    const int rem  = cell - roi * (POOL * POOL);
    const int py   = rem / POOL;
    const int px   = rem - py * POOL;

    const int x = rois[roi * 4 + 0];
    const int y = rois[roi * 4 + 1];
    const int w = rois[roi * 4 + 2];
    const int h = rois[roi * 4 + 3];

    const float hf = (float)h;
    const float wf = (float)w;

    // half-pixel-center source coords, clamped (matches tf.image.resize bilinear)
    float ys = ((float)py + 0.5f) * hf * (1.0f / POOL) - 0.5f;
    float xs = ((float)px + 0.5f) * wf * (1.0f / POOL) - 0.5f;
    ys = fminf(fmaxf(ys, 0.0f), hf - 1.0f);
    xs = fminf(fmaxf(xs, 0.0f), wf - 1.0f);

    const int y0 = (int)floorf(ys);
    const int x0 = (int)floorf(xs);
    const int y1 = min(y0 + 1, h - 1);
    const int x1 = min(x0 + 1, w - 1);
    const float fy = ys - (float)y0;
    const float fx = xs - (float)x0;

    const int ay0 = y + y0, ay1 = y + y1;
    const int ax0 = x + x0, ax1 = x + x1;

    const int co = lane * 8;                  // this thread's channel offset
    const float* p00 = img + ((size_t)(ay0 * IMG_W + ax0)) * CH + co;
    const float* p01 = img + ((size_t)(ay0 * IMG_W + ax1)) * CH + co;
    const float* p10 = img + ((size_t)(ay1 * IMG_W + ax0)) * CH + co;
    const float* p11 = img + ((size_t)(ay1 * IMG_W + ax1)) * CH + co;

    const float w00 = (1.0f - fy) * (1.0f - fx);
    const float w01 = (1.0f - fy) * fx;
    const float w10 = fy * (1.0f - fx);
    const float w11 = fy * fx;

    // 4 x 256-bit loads in flight (128B payload per thread)
    const f8 a = ldg256(p00);
    const f8 b = ldg256(p01);
    const f8 c = ldg256(p10);
    const f8 d = ldg256(p11);

    float4 r0, r1;
    r0.x = a.v[0] * w00 + b.v[0] * w01 + c.v[0] * w10 + d.v[0] * w11;
    r0.y = a.v[1] * w00 + b.v[1] * w01 + c.v[1] * w10 + d.v[1] * w11;
    r0.z = a.v[2] * w00 + b.v[2] * w01 + c.v[2] * w10 + d.v[2] * w11;
    r0.w = a.v[3] * w00 + b.v[3] * w01 + c.v[3] * w10 + d.v[3] * w11;
    r1.x = a.v[4] * w00 + b.v[4] * w01 + c.v[4] * w10 + d.v[4] * w11;
    r1.y = a.v[5] * w00 + b.v[5] * w01 + c.v[5] * w10 + d.v[5] * w11;
    r1.z = a.v[6] * w00 + b.v[6] * w01 + c.v[6] * w10 + d.v[6] * w11;
    r1.w = a.v[7] * w00 + b.v[7] * w01 + c.v[7] * w10 + d.v[7] * w11;

    // streaming stores: keep the image resident in L2 (R13 A/B: stcs wins)
    float4* o = (float4*)(out + (size_t)cell * CH + co);
    __stcs(o + 0, r0);
    __stcs(o + 1, r1);
}

extern "C" void kernel_launch(void* const* d_in, const int* in_sizes, int n_in,
                              void* d_out, int out_size) {
    const float* img  = (const float*)d_in[0];
    const int*   rois = (const int*)d_in[1];
    float*       out  = (float*)d_out;

    const int n_cells = NUM_ROIS * POOL * POOL;   // 25088
    roi_pool_kernel<<<n_cells / 2, 256>>>(img, rois, out);
}

// round 15
// speedup vs baseline: 1.2655x; 1.2655x over previous
#include <cuda_runtime.h>
#include <cstdint>

#define POOL 7
#define NUM_ROIS 512
#define IMG_H 128
#define IMG_W 128
#define CH 1024

// FINAL (R3 structure, best of 7 structural designs at 35.0us):
// 2 cells per 256-thread block: threads 0-127 -> cell0, 128-255 -> cell1.
// Each thread handles float4 indices lane and lane+128 (both warp-coalesced),
// giving 8 outstanding 16B loads per thread with no wavefront inflation.
// __stcs streaming stores keep the 64MB image L2-resident (R13 A/B verified).
__global__ __launch_bounds__(256, 8)
void roi_pool_kernel(const float* __restrict__ img,
                     const int* __restrict__ rois,
                     float* __restrict__ out) {
    const int half = threadIdx.x >> 7;        // 0 or 1
    const int lane = threadIdx.x & 127;       // 0..127
    const int cell = blockIdx.x * 2 + half;   // roi*49 + py*7 + px

    const int roi  = cell / (POOL * POOL);
    const int rem  = cell - roi * (POOL * POOL);
    const int py   = rem / POOL;
    const int px   = rem - py * POOL;

    const int x = rois[roi * 4 + 0];
    const int y = rois[roi * 4 + 1];
    const int w = rois[roi * 4 + 2];
    const int h = rois[roi * 4 + 3];

    const float hf = (float)h;
    const float wf = (float)w;

    // half-pixel-center source coords, clamped (matches tf.image.resize bilinear)
    float ys = ((float)py + 0.5f) * hf * (1.0f / POOL) - 0.5f;
    float xs = ((float)px + 0.5f) * wf * (1.0f / POOL) - 0.5f;
    ys = fminf(fmaxf(ys, 0.0f), hf - 1.0f);
    xs = fminf(fmaxf(xs, 0.0f), wf - 1.0f);

    const int y0 = (int)floorf(ys);
    const int x0 = (int)floorf(xs);
    const int y1 = min(y0 + 1, h - 1);
    const int x1 = min(x0 + 1, w - 1);
    const float fy = ys - (float)y0;
    const float fx = xs - (float)x0;

    const int ay0 = y + y0, ay1 = y + y1;
    const int ax0 = x + x0, ax1 = x + x1;

    const float4* p00 = (const float4*)(img + ((size_t)(ay0 * IMG_W + ax0)) * CH);
    const float4* p01 = (const float4*)(img + ((size_t)(ay0 * IMG_W + ax1)) * CH);
    const float4* p10 = (const float4*)(img + ((size_t)(ay1 * IMG_W + ax0)) * CH);
    const float4* p11 = (const float4*)(img + ((size_t)(ay1 * IMG_W + ax1)) * CH);

    const float w00 = (1.0f - fy) * (1.0f - fx);
    const float w01 = (1.0f - fy) * fx;
    const float w10 = fy * (1.0f - fx);
    const float w11 = fy * fx;

    const int i0 = lane;          // coalesced: warp covers 512B contiguous
    const int i1 = lane + 128;    // coalesced: warp covers 512B contiguous

    // 8 independent loads in flight before any dependent math
    float4 a0 = __ldg(p00 + i0);
    float4 b0 = __ldg(p01 + i0);
    float4 c0 = __ldg(p10 + i0);
    float4 d0 = __ldg(p11 + i0);
    float4 a1 = __ldg(p00 + i1);
    float4 b1 = __ldg(p01 + i1);
    float4 c1 = __ldg(p10 + i1);
    float4 d1 = __ldg(p11 + i1);

    float4 r0, r1;
    r0.x = a0.x * w00 + b0.x * w01 + c0.x * w10 + d0.x * w11;
    r0.y = a0.y * w00 + b0.y * w01 + c0.y * w10 + d0.y * w11;
    r0.z = a0.z * w00 + b0.z * w01 + c0.z * w10 + d0.z * w11;
    r0.w = a0.w * w00 + b0.w * w01 + c0.w * w10 + d0.w * w11;
    r1.x = a1.x * w00 + b1.x * w01 + c1.x * w10 + d1.x * w11;
    r1.y = a1.y * w00 + b1.y * w01 + c1.y * w10 + d1.y * w11;
    r1.z = a1.z * w00 + b1.z * w01 + c1.z * w10 + d1.z * w11;
    r1.w = a1.w * w00 + b1.w * w01 + c1.w * w10 + d1.w * w11;

    // streaming stores: don't let the 103MB output evict the 64MB image from L2
    float4* o = (float4*)(out + (size_t)cell * CH);
    __stcs(o + i0, r0);
    __stcs(o + i1, r1);
}

extern "C" void kernel_launch(void* const* d_in, const int* in_sizes, int n_in,
                              void* d_out, int out_size) {
    const float* img  = (const float*)d_in[0];
    const int*   rois = (const int*)d_in[1];
    float*       out  = (float*)d_out;

    const int n_cells = NUM_ROIS * POOL * POOL;   // 25088
    roi_pool_kernel<<<n_cells / 2, 256>>>(img, rois, out);
}

// round 16
// speedup vs baseline: 1.2748x; 1.0074x over previous
#include <cuda_runtime.h>
#include <cstdint>

#define POOL 7
#define NUM_ROIS 512
#define IMG_H 128
#define IMG_W 128
#define CH 1024

// R3 compute structure (35.0us optimum) with ONE change: output staged in smem
// and written by a single 8KB cp.async.bulk (TMA) store per block with
// L2::evict_first hint (same policy as the proven __stcs). Removes all STG
// wavefronts from l1tex (~20% of its traffic).
__global__ __launch_bounds__(256, 8)
void roi_pool_kernel(const float* __restrict__ img,
                     const int* __restrict__ rois,
                     float* __restrict__ out) {
    __shared__ float4 sbuf[512];              // 2 cells x 256 float4 = 8KB

    const int half = threadIdx.x >> 7;        // 0 or 1
    const int lane = threadIdx.x & 127;       // 0..127
    const int cell = blockIdx.x * 2 + half;   // roi*49 + py*7 + px

    const int roi  = cell / (POOL * POOL);
    const int rem  = cell - roi * (POOL * POOL);
    const int py   = rem / POOL;
    const int px   = rem - py * POOL;

    const int x = rois[roi * 4 + 0];
    const int y = rois[roi * 4 + 1];
    const int w = rois[roi * 4 + 2];
    const int h = rois[roi * 4 + 3];

    const float hf = (float)h;
    const float wf = (float)w;

    // half-pixel-center source coords, clamped (matches tf.image.resize bilinear)
    float ys = ((float)py + 0.5f) * hf * (1.0f / POOL) - 0.5f;
    float xs = ((float)px + 0.5f) * wf * (1.0f / POOL) - 0.5f;
    ys = fminf(fmaxf(ys, 0.0f), hf - 1.0f);
    xs = fminf(fmaxf(xs, 0.0f), wf - 1.0f);

    const int y0 = (int)floorf(ys);
    const int x0 = (int)floorf(xs);
    const int y1 = min(y0 + 1, h - 1);
    const int x1 = min(x0 + 1, w - 1);
    const float fy = ys - (float)y0;
    const float fx = xs - (float)x0;

    const int ay0 = y + y0, ay1 = y + y1;
    const int ax0 = x + x0, ax1 = x + x1;

    const float4* p00 = (const float4*)(img + ((size_t)(ay0 * IMG_W + ax0)) * CH);
    const float4* p01 = (const float4*)(img + ((size_t)(ay0 * IMG_W + ax1)) * CH);
    const float4* p10 = (const float4*)(img + ((size_t)(ay1 * IMG_W + ax0)) * CH);
    const float4* p11 = (const float4*)(img + ((size_t)(ay1 * IMG_W + ax1)) * CH);

    const float w00 = (1.0f - fy) * (1.0f - fx);
    const float w01 = (1.0f - fy) * fx;
    const float w10 = fy * (1.0f - fx);
    const float w11 = fy * fx;

    const int i0 = lane;          // coalesced: warp covers 512B contiguous
    const int i1 = lane + 128;    // coalesced: warp covers 512B contiguous

    // 8 independent loads in flight before any dependent math
    float4 a0 = __ldg(p00 + i0);
    float4 b0 = __ldg(p01 + i0);
    float4 c0 = __ldg(p10 + i0);
    float4 d0 = __ldg(p11 + i0);
    float4 a1 = __ldg(p00 + i1);
    float4 b1 = __ldg(p01 + i1);
    float4 c1 = __ldg(p10 + i1);
    float4 d1 = __ldg(p11 + i1);

    float4 r0, r1;
    r0.x = a0.x * w00 + b0.x * w01 + c0.x * w10 + d0.x * w11;
    r0.y = a0.y * w00 + b0.y * w01 + c0.y * w10 + d0.y * w11;
    r0.z = a0.z * w00 + b0.z * w01 + c0.z * w10 + d0.z * w11;
    r0.w = a0.w * w00 + b0.w * w01 + c0.w * w10 + d0.w * w11;
    r1.x = a1.x * w00 + b1.x * w01 + c1.x * w10 + d1.x * w11;
    r1.y = a1.y * w00 + b1.y * w01 + c1.y * w10 + d1.y * w11;
    r1.z = a1.z * w00 + b1.z * w01 + c1.z * w10 + d1.z * w11;
    r1.w = a1.w * w00 + b1.w * w01 + c1.w * w10 + d1.w * w11;

    // stage into smem (conflict-free STS.128)
    sbuf[half * 256 + i0] = r0;
    sbuf[half * 256 + i1] = r1;
    __syncthreads();

    // one 8KB TMA bulk store for both cells (contiguous in out), evict_first
    if (threadIdx.x == 0) {
        float* dst = out + (size_t)(blockIdx.x * 2) * CH;
        uint32_t src;
        asm("{ .reg .u64 t; cvta.to.shared.u64 t, %1; cvt.u32.u64 %0, t; }"
            : "=r"(src) : "l"(sbuf));
        asm volatile("fence.proxy.async.shared::cta;" ::: "memory");
        asm volatile(
            "{\n\t"
            ".reg .b64 pol;\n\t"
            "createpolicy.fractional.L2::evict_first.b64 pol, 1.0;\n\t"
            "cp.async.bulk.global.shared::cta.bulk_group.L2::cache_hint "
            "[%0], [%1], %2, pol;\n\t"
            "cp.async.bulk.commit_group;\n\t"
            "}"
            :: "l"(dst), "r"(src), "r"((uint32_t)8192) : "memory");
        asm volatile("cp.async.bulk.wait_group 0;" ::: "memory");
    }
}

extern "C" void kernel_launch(void* const* d_in, const int* in_sizes, int n_in,
                              void* d_out, int out_size) {
    const float* img  = (const float*)d_in[0];
    const int*   rois = (const int*)d_in[1];
    float*       out  = (float*)d_out;

    const int n_cells = NUM_ROIS * POOL * POOL;   // 25088
    roi_pool_kernel<<<n_cells / 2, 256>>>(img, rois, out);
}